// round 1
// baseline (speedup 1.0000x reference)
#include <cuda_runtime.h>
#include <cuda_bf16.h>
#include <cstdint>

// ---------------------------------------------------------------------------
// GINConvolution:
//   h   = x @ W                      [N,128]
//   agg[i] = sum_{e: row[e]==i} vals[e] * h[col[e]]
//   out = relu((1+eps)*h + agg + bias)
//
// Inputs (metadata order): x[N*128] f32, kernel[128*128] f32, bias[128] f32,
//   eps[1] f32, adj_vals[E] f32, row[E] i32, col[E] i32.  Output: [N,128] f32.
// ---------------------------------------------------------------------------

#define N_NODES_MAX 100000
#define UNITS 128

// Scratch for h (allocation-free rule: use __device__ global array).
__device__ float g_h[N_NODES_MAX * UNITS];

// ---------------------------------------------------------------------------
// Kernel 1: tiled fp32 GEMM, fused epilogue:
//   g_h[row]  = h_row
//   out[row]  = (1+eps)*h_row + bias    (pre-aggregation accumulator)
// Block: 256 threads (tx=32 cols-of-4, ty=8 rows-of-8). Tile: 64 rows x 128 cols.
// ---------------------------------------------------------------------------
#define TM 64

__global__ __launch_bounds__(256) void gin_gemm_kernel(
    const float* __restrict__ x,
    const float* __restrict__ W,
    const float* __restrict__ bias,
    const float* __restrict__ eps,
    float* __restrict__ out,
    int n_nodes)
{
    __shared__ float xs[TM][UNITS];

    const int block_row = blockIdx.x * TM;
    const int tid = threadIdx.x;

    // Load x tile (64 rows x 128 cols) as float4, guarded for the tail block.
    {
        const float4* x4 = reinterpret_cast<const float4*>(x);
        float4* xs4 = reinterpret_cast<float4*>(&xs[0][0]);
        #pragma unroll
        for (int i = tid; i < TM * 32; i += 256) {
            int r = i >> 5;               // row within tile
            int gr = block_row + r;
            float4 v = make_float4(0.f, 0.f, 0.f, 0.f);
            if (gr < n_nodes) v = x4[gr * 32 + (i & 31)];
            xs4[i] = v;
        }
    }
    __syncthreads();

    const int tx = tid & 31;   // covers 4 cols: 4*tx .. 4*tx+3
    const int ty = tid >> 5;   // covers 8 rows: ty, ty+8, ..., ty+56

    float acc[8][4];
    #pragma unroll
    for (int i = 0; i < 8; i++)
        #pragma unroll
        for (int j = 0; j < 4; j++) acc[i][j] = 0.f;

    const float4* W4 = reinterpret_cast<const float4*>(W);

    #pragma unroll 4
    for (int k = 0; k < UNITS; k++) {
        float4 w = W4[k * 32 + tx];   // W[k][4tx .. 4tx+3], coalesced, L1-hot
        #pragma unroll
        for (int i = 0; i < 8; i++) {
            float a = xs[ty + 8 * i][k];   // warp-broadcast (same addr per warp)
            acc[i][0] += a * w.x;
            acc[i][1] += a * w.y;
            acc[i][2] += a * w.z;
            acc[i][3] += a * w.w;
        }
    }

    const float escale = 1.0f + eps[0];
    const float4 b = reinterpret_cast<const float4*>(bias)[tx];
    float4* h4 = reinterpret_cast<float4*>(g_h);
    float4* o4 = reinterpret_cast<float4*>(out);

    #pragma unroll
    for (int i = 0; i < 8; i++) {
        int gr = block_row + ty + 8 * i;
        if (gr < n_nodes) {
            float4 hv = make_float4(acc[i][0], acc[i][1], acc[i][2], acc[i][3]);
            h4[gr * 32 + tx] = hv;
            float4 ov;
            ov.x = escale * hv.x + b.x;
            ov.y = escale * hv.y + b.y;
            ov.z = escale * hv.z + b.z;
            ov.w = escale * hv.w + b.w;
            o4[gr * 32 + tx] = ov;
        }
    }
}

// ---------------------------------------------------------------------------
// Kernel 2: edge scatter. One warp per edge; each lane handles one float4
// chunk (32 lanes * 4 = 128 floats). Vector reduction (red.global.add.v4.f32)
// quarters the atomic instruction count vs scalar atomicAdd.
// ---------------------------------------------------------------------------
__device__ __forceinline__ void red_add_v4(float* ptr, float a, float b, float c, float d) {
    asm volatile("red.global.add.v4.f32 [%0], {%1, %2, %3, %4};"
                 :: "l"(ptr), "f"(a), "f"(b), "f"(c), "f"(d)
                 : "memory");
}

__global__ __launch_bounds__(256) void gin_edge_kernel(
    const float* __restrict__ vals,
    const int* __restrict__ row,
    const int* __restrict__ col,
    float* __restrict__ out,
    int n_edges)
{
    const int e = (blockIdx.x * blockDim.x + threadIdx.x) >> 5;
    if (e >= n_edges) return;
    const int lane = threadIdx.x & 31;

    const int r = row[e];
    const int c = col[e];
    const float v = vals[e];

    const float4 hv = reinterpret_cast<const float4*>(g_h)[c * 32 + lane];
    float* dst = out + (size_t)r * UNITS + lane * 4;
    red_add_v4(dst, v * hv.x, v * hv.y, v * hv.z, v * hv.w);
}

// ---------------------------------------------------------------------------
// Kernel 3: in-place ReLU.
// ---------------------------------------------------------------------------
__global__ __launch_bounds__(256) void gin_relu_kernel(float* __restrict__ out, int n4)
{
    int i = blockIdx.x * blockDim.x + threadIdx.x;
    if (i >= n4) return;
    float4* o4 = reinterpret_cast<float4*>(out);
    float4 v = o4[i];
    v.x = fmaxf(v.x, 0.f);
    v.y = fmaxf(v.y, 0.f);
    v.z = fmaxf(v.z, 0.f);
    v.w = fmaxf(v.w, 0.f);
    o4[i] = v;
}

// ---------------------------------------------------------------------------
extern "C" void kernel_launch(void* const* d_in, const int* in_sizes, int n_in,
                              void* d_out, int out_size)
{
    const float* x     = (const float*)d_in[0];
    const float* W     = (const float*)d_in[1];
    const float* bias  = (const float*)d_in[2];
    const float* eps   = (const float*)d_in[3];
    const float* vals  = (const float*)d_in[4];
    const int*   row   = (const int*)d_in[5];
    const int*   col   = (const int*)d_in[6];
    float* out = (float*)d_out;

    const int n_nodes = in_sizes[0] / UNITS;
    const int n_edges = in_sizes[4];

    // 1) h = x @ W ; out = (1+eps)*h + bias
    {
        int grid = (n_nodes + TM - 1) / TM;
        gin_gemm_kernel<<<grid, 256>>>(x, W, bias, eps, out, n_nodes);
    }

    // 2) out[row] += val * h[col]  (warp per edge, vector reductions)
    {
        long long total_threads = (long long)n_edges * 32;
        int grid = (int)((total_threads + 255) / 256);
        gin_edge_kernel<<<grid, 256>>>(vals, row, col, out, n_edges);
    }

    // 3) relu in place
    {
        int n4 = n_nodes * (UNITS / 4);
        int grid = (n4 + 255) / 256;
        gin_relu_kernel<<<grid, 256>>>(out, n4);
    }
}